// round 1
// baseline (speedup 1.0000x reference)
#include <cuda_runtime.h>

// Sizes (fixed by the problem):
// B=64, NIN=512, H1=H2=1024, NOUT=512, COND=64, FC=1
//
// out[b,o] = sum_i sigmoid(f1[b,i]*f2[b,o]) * (m*W)[o,i] * x[b,i]
// sigmoid(z) = 0.5 + 0.5*tanh(z/2); fold the 1/2 into f2 at precompute time.

// ---------------- device scratch (static allocation only) ----------------
__device__ float g_MW0[1024 * 512];
__device__ float g_MW1[1024 * 1024];
__device__ float g_MW2[512 * 1024];
__device__ float g_f1a[3 * 64 * 1024];   // f1 per layer, slot stride 65536, row stride I
__device__ float g_f2a[3 * 64 * 1024];   // 0.5*f2 per layer, slot stride 65536, row stride O
__device__ float g_partA[4 * 64 * 1024]; // split-K partials, [s][b*O+o], s stride 65536
__device__ float g_partB[4 * 64 * 1024];

__device__ __forceinline__ float tanh_fast(float x) {
    float r;
    asm("tanh.approx.f32 %0, %1;" : "=f"(r) : "f"(x));
    return r;
}

// ---------------- MW = mask * W (elementwise) ----------------
__global__ void prep_mw_kernel(const float* __restrict__ m0, const float* __restrict__ w0,
                               const float* __restrict__ m1, const float* __restrict__ w1,
                               const float* __restrict__ m2, const float* __restrict__ w2) {
    int idx = blockIdx.x * blockDim.x + threadIdx.x;
    if (idx < 524288) {
        g_MW0[idx] = m0[idx] * w0[idx];
    } else if (idx < 524288 + 1048576) {
        int k = idx - 524288;
        g_MW1[k] = m1[k] * w1[k];
    } else if (idx < 2097152) {
        int k = idx - 1572864;
        g_MW2[k] = m2[k] * w2[k];
    }
}

// ---------------- all six conditioning GEMVs in one kernel ----------------
// f[b,j] = (sum_c u[b,c]*w[j,c] + bias[j]) * scale
// block: 256 threads = 64 batches x 4 j's. grid: (256, 6)
__global__ void cond_kernel(const float* __restrict__ u,
                            const float* __restrict__ w0, const float* __restrict__ b0,
                            const float* __restrict__ w1, const float* __restrict__ b1,
                            const float* __restrict__ w2, const float* __restrict__ b2,
                            const float* __restrict__ w3, const float* __restrict__ b3,
                            const float* __restrict__ w4, const float* __restrict__ b4,
                            const float* __restrict__ w5, const float* __restrict__ b5) {
    __shared__ float us[64 * 65];  // padded, conflict-free along b
    int tid = threadIdx.x;
    for (int k = tid; k < 64 * 64; k += 256) {
        us[(k >> 6) * 65 + (k & 63)] = u[k];
    }
    __syncthreads();

    const float* w;
    const float* bias;
    int J;
    float scale;
    float* dst;
    switch (blockIdx.y) {
        case 0:  w = w0; bias = b0; J = 512;  scale = 1.0f; dst = g_f1a;          break;
        case 1:  w = w1; bias = b1; J = 1024; scale = 0.5f; dst = g_f2a;          break;
        case 2:  w = w2; bias = b2; J = 1024; scale = 1.0f; dst = g_f1a + 65536;  break;
        case 3:  w = w3; bias = b3; J = 1024; scale = 0.5f; dst = g_f2a + 65536;  break;
        case 4:  w = w4; bias = b4; J = 1024; scale = 1.0f; dst = g_f1a + 131072; break;
        default: w = w5; bias = b5; J = 512;  scale = 0.5f; dst = g_f2a + 131072; break;
    }

    int b = tid & 63;
    int jj = tid >> 6;
    int j = blockIdx.x * 4 + jj;
    if (j >= J) return;

    const float* wr = w + j * 64;
    float acc = 0.0f;
#pragma unroll
    for (int c = 0; c < 64; ++c) {
        acc = __fmaf_rn(wr[c], us[b * 65 + c], acc);
    }
    dst[b * J + j] = (acc + bias[j]) * scale;
}

// ---------------- main layer kernel ----------------
// block (32,4): lane tx owns outputs oBase+tx and oBase+tx+32; ty owns one batch.
// grid (O/64, 16, NS=4) split-K over i; partial sums -> partdst[s][b*O+o].
// x is either a dense buffer (xparts==1) or the sum of 4 split-K partials.
template <int I, int O>
__global__ void __launch_bounds__(128) layer_kernel(
    const float* __restrict__ xsrc, int xparts,
    const float* __restrict__ f1, const float* __restrict__ f2,
    const float* __restrict__ MW, float* __restrict__ partdst) {
    constexpr int NS = 4;
    constexpr int ISEG = I / NS;  // 128 or 256

    __shared__ float MWs[64][65];   // [oo][ii], padded: conflict-free LDS on tx stride
    __shared__ float2 fxs[4][64];   // [bb][ii] = (f1, x) — warp-uniform reads

    int tx = threadIdx.x, ty = threadIdx.y;
    int tid = ty * 32 + tx;
    int oBase = blockIdx.x * 64;
    int bBase = blockIdx.y * 4;
    int s = blockIdx.z;
    int iBase0 = s * ISEG;

    float f2r0 = f2[(bBase + ty) * O + oBase + tx];
    float f2r1 = f2[(bBase + ty) * O + oBase + tx + 32];
    float acc0 = 0.0f, acc1 = 0.0f;

    for (int ch = 0; ch < ISEG / 64; ++ch) {
        int iB = iBase0 + ch * 64;

        // stage MW tile (coalesced float2 LDG; STS 2-way conflict worst case)
        {
            int c2 = tid & 31;
            for (int row = tid >> 5; row < 64; row += 4) {
                float2 v = *(const float2*)(MW + (size_t)(oBase + row) * I + iB + c2 * 2);
                MWs[row][c2 * 2] = v.x;
                MWs[row][c2 * 2 + 1] = v.y;
            }
        }
        // stage (f1, x); x may be a 4-way partial sum from the previous layer
        for (int k = tid; k < 256; k += 128) {
            int bb = k >> 6, ii = k & 63;
            int b = bBase + bb;
            int gi = iB + ii;
            float f1v = f1[b * I + gi];
            float xv;
            if (xparts == 1) {
                xv = xsrc[b * I + gi];
            } else {
                xv = xsrc[b * I + gi] + xsrc[65536 + b * I + gi] +
                     xsrc[131072 + b * I + gi] + xsrc[196608 + b * I + gi];
            }
            fxs[bb][ii] = make_float2(f1v, xv);
        }
        __syncthreads();

#pragma unroll 8
        for (int ii = 0; ii < 64; ++ii) {
            float2 fx = fxs[ty][ii];
            float mw0 = MWs[tx][ii];
            float mw1 = MWs[tx + 32][ii];
            float h0 = tanh_fast(fx.x * f2r0);
            float h1 = tanh_fast(fx.x * f2r1);
            float w0 = __fmaf_rn(h0, 0.5f, 0.5f);  // sigmoid = 0.5 + 0.5*tanh
            float w1 = __fmaf_rn(h1, 0.5f, 0.5f);
            acc0 = __fmaf_rn(w0, mw0 * fx.y, acc0);
            acc1 = __fmaf_rn(w1, mw1 * fx.y, acc1);
        }
        __syncthreads();
    }

    partdst[s * 65536 + (bBase + ty) * O + oBase + tx] = acc0;
    partdst[s * 65536 + (bBase + ty) * O + oBase + tx + 32] = acc1;
}

// ---------------- final reduce: sum 4 partials -> d_out ----------------
__global__ void reduce_out_kernel(float* __restrict__ out) {
    int k = blockIdx.x * 256 + threadIdx.x;
    if (k < 64 * 512) {
        out[k] = g_partA[k] + g_partA[65536 + k] + g_partA[131072 + k] + g_partA[196608 + k];
    }
}

extern "C" void kernel_launch(void* const* d_in, const int* in_sizes, int n_in,
                              void* d_out, int out_size) {
    const float* x     = (const float*)d_in[0];
    const float* u     = (const float*)d_in[1];
    const float* mask0 = (const float*)d_in[2];
    const float* mask1 = (const float*)d_in[3];
    const float* mask2 = (const float*)d_in[4];
    const float* W0    = (const float*)d_in[5];
    const float* W1    = (const float*)d_in[6];
    const float* W2    = (const float*)d_in[7];
    const float* a0_w  = (const float*)d_in[8];
    const float* a0_b  = (const float*)d_in[9];
    const float* b0_w  = (const float*)d_in[10];
    const float* b0_b  = (const float*)d_in[11];
    const float* a1_w  = (const float*)d_in[12];
    const float* a1_b  = (const float*)d_in[13];
    const float* b1_w  = (const float*)d_in[14];
    const float* b1_b  = (const float*)d_in[15];
    const float* a2_w  = (const float*)d_in[16];
    const float* a2_b  = (const float*)d_in[17];
    const float* b2_w  = (const float*)d_in[18];
    const float* b2_b  = (const float*)d_in[19];
    float* out = (float*)d_out;

    float* pMW0;  cudaGetSymbolAddress((void**)&pMW0, g_MW0);
    float* pMW1;  cudaGetSymbolAddress((void**)&pMW1, g_MW1);
    float* pMW2;  cudaGetSymbolAddress((void**)&pMW2, g_MW2);
    float* pf1;   cudaGetSymbolAddress((void**)&pf1, g_f1a);
    float* pf2;   cudaGetSymbolAddress((void**)&pf2, g_f2a);
    float* pA;    cudaGetSymbolAddress((void**)&pA, g_partA);
    float* pB;    cudaGetSymbolAddress((void**)&pB, g_partB);

    // 1) MW = mask * W
    prep_mw_kernel<<<8192, 256>>>(mask0, W0, mask1, W1, mask2, W2);

    // 2) all f1 / (0.5*f2) vectors
    cond_kernel<<<dim3(256, 6), 256>>>(u,
        a0_w, a0_b, b0_w, b0_b,
        a1_w, a1_b, b1_w, b1_b,
        a2_w, a2_b, b2_w, b2_b);

    // 3) layer 0: x(64x512) -> partials A (O=1024)
    layer_kernel<512, 1024><<<dim3(16, 16, 4), dim3(32, 4)>>>(
        x, 1, pf1, pf2, pMW0, pA);

    // 4) layer 1: h1 = sum(partials A) -> partials B (O=1024)
    layer_kernel<1024, 1024><<<dim3(16, 16, 4), dim3(32, 4)>>>(
        pA, 4, pf1 + 65536, pf2 + 65536, pMW1, pB);

    // 5) layer 2: h2 = sum(partials B) -> partials A (O=512)
    layer_kernel<1024, 512><<<dim3(8, 16, 4), dim3(32, 4)>>>(
        pB, 4, pf1 + 131072, pf2 + 131072, pMW2, pA);

    // 6) final reduce -> d_out (64x512)
    reduce_out_kernel<<<128, 256>>>(out);
}

// round 2
// speedup vs baseline: 1.2355x; 1.2355x over previous
#include <cuda_runtime.h>

// B=64, NIN=512, H1=H2=1024, NOUT=512, COND=64, FC=1
// out[b,o] = sum_i sigmoid(f1[b,i]*f2[b,o]) * (m*W)[o,i] * x[b,i]
// sigmoid(z) = 0.5 + 0.5*tanh(z/2); the 1/2 is folded into f2 at precompute.

// ---------------- device scratch ----------------
__device__ float g_MW0[1024 * 512];
__device__ float g_MW1[1024 * 1024];
__device__ float g_MW2[512 * 1024];
__device__ float g_f1a[3 * 64 * 1024];   // f1 per layer, slot stride 65536
__device__ float g_f2a[3 * 64 * 1024];   // 0.5*f2 per layer, slot stride 65536
__device__ float g_partA[2097152];       // split-K partials (8MB)
__device__ float g_partB[2097152];       // split-K partials (8MB)
__device__ float g_h1[65536];
__device__ float g_h2[65536];

__device__ __forceinline__ float tanh_fast(float x) {
    float r;
    asm("tanh.approx.f32 %0, %1;" : "=f"(r) : "f"(x));
    return r;
}

// ---------------- MW = mask * W (float4 vectorized) ----------------
__global__ void prep_mw_kernel(const float4* __restrict__ m0, const float4* __restrict__ w0,
                               const float4* __restrict__ m1, const float4* __restrict__ w1,
                               const float4* __restrict__ m2, const float4* __restrict__ w2) {
    int idx = blockIdx.x * blockDim.x + threadIdx.x;  // 524288 float4s total
    float4 m, w;
    float4* dst;
    if (idx < 131072) {
        m = m0[idx]; w = w0[idx]; dst = (float4*)g_MW0 + idx;
    } else if (idx < 393216) {
        int k = idx - 131072;
        m = m1[k]; w = w1[k]; dst = (float4*)g_MW1 + k;
    } else if (idx < 524288) {
        int k = idx - 393216;
        m = m2[k]; w = w2[k]; dst = (float4*)g_MW2 + k;
    } else {
        return;
    }
    *dst = make_float4(m.x * w.x, m.y * w.y, m.z * w.z, m.w * w.w);
}

// ---------------- all six conditioning GEMVs ----------------
// f[b,j] = (sum_c u[b,c]*w[j,c] + bias[j]) * scale ; grid (256, 6), 256 thr
__global__ void cond_kernel(const float* __restrict__ u,
                            const float* __restrict__ w0, const float* __restrict__ b0,
                            const float* __restrict__ w1, const float* __restrict__ b1,
                            const float* __restrict__ w2, const float* __restrict__ b2,
                            const float* __restrict__ w3, const float* __restrict__ b3,
                            const float* __restrict__ w4, const float* __restrict__ b4,
                            const float* __restrict__ w5, const float* __restrict__ b5) {
    __shared__ float us[64 * 65];
    int tid = threadIdx.x;
    for (int k = tid; k < 64 * 64; k += 256)
        us[(k >> 6) * 65 + (k & 63)] = u[k];
    __syncthreads();

    const float* w; const float* bias;
    int J; float scale; float* dst;
    switch (blockIdx.y) {
        case 0:  w = w0; bias = b0; J = 512;  scale = 1.0f; dst = g_f1a;          break;
        case 1:  w = w1; bias = b1; J = 1024; scale = 0.5f; dst = g_f2a;          break;
        case 2:  w = w2; bias = b2; J = 1024; scale = 1.0f; dst = g_f1a + 65536;  break;
        case 3:  w = w3; bias = b3; J = 1024; scale = 0.5f; dst = g_f2a + 65536;  break;
        case 4:  w = w4; bias = b4; J = 1024; scale = 1.0f; dst = g_f1a + 131072; break;
        default: w = w5; bias = b5; J = 512;  scale = 0.5f; dst = g_f2a + 131072; break;
    }

    int b = tid & 63;
    int jj = tid >> 6;
    int j = blockIdx.x * 4 + jj;
    if (j >= J) return;

    const float* wr = w + j * 64;
    float acc = 0.0f;
#pragma unroll
    for (int c = 0; c < 64; ++c)
        acc = __fmaf_rn(wr[c], us[b * 65 + c], acc);
    dst[b * J + j] = (acc + bias[j]) * scale;
}

// ---------------- main layer kernel ----------------
// block (32,4). Thread: outputs oBase+2tx, oBase+2tx+1; batches bBase+ty, bBase+ty+4.
// grid (O/64, B/8, NS). Each CTA handles ISEG = I/NS = 32 inputs (single chunk).
// ILP-4: 4 independent sigmoid chains per thread.
template <int I, int O, int NS>
__global__ void __launch_bounds__(128) layer_kernel(
    const float* __restrict__ xsrc,
    const float* __restrict__ f1, const float* __restrict__ f2,
    const float* __restrict__ MW, float* __restrict__ partdst) {
    constexpr int ISEG = I / NS;          // 32
    constexpr int PITCH = 66;             // even pitch: aligned float2, conflict-free

    __shared__ float MWs[ISEG][PITCH];    // transposed [i][o]
    __shared__ float2 fxs[8][ISEG];       // [bb][ii] = (f1, x)

    int tx = threadIdx.x, ty = threadIdx.y;
    int tid = ty * 32 + tx;
    int oBase = blockIdx.x * 64;
    int bBase = blockIdx.y * 8;
    int iBase = blockIdx.z * ISEG;

    // stage MW tile transposed: thread loads float4 along i, scatters to [i][o]
    {
        // 64 rows x (ISEG/4) float4 = 512 float4s; 128 threads x 4
        int i4 = tid & (ISEG / 4 - 1);        // 0..7
        int oo = tid / (ISEG / 4);            // 0..15, step 16 per r
#pragma unroll
        for (int r = 0; r < 4; ++r) {
            int o = oo + r * 16;
            float4 v = *(const float4*)(MW + (size_t)(oBase + o) * I + iBase + i4 * 4);
            MWs[i4 * 4 + 0][o] = v.x;
            MWs[i4 * 4 + 1][o] = v.y;
            MWs[i4 * 4 + 2][o] = v.z;
            MWs[i4 * 4 + 3][o] = v.w;
        }
    }
    // stage (f1, x): 8 batches x ISEG = 256 elements, 2 per thread
    {
#pragma unroll
        for (int r = 0; r < 2; ++r) {
            int k = tid + r * 128;
            int bb = k >> 5;                  // ISEG=32
            int ii = k & 31;
            int b = bBase + bb;
            int gi = iBase + ii;
            fxs[bb][ii] = make_float2(f1[b * I + gi], xsrc[b * I + gi]);
        }
    }

    int b0 = bBase + ty, b1 = bBase + ty + 4;
    int o0 = oBase + 2 * tx;
    float f2_00 = f2[b0 * O + o0], f2_01 = f2[b0 * O + o0 + 1];
    float f2_10 = f2[b1 * O + o0], f2_11 = f2[b1 * O + o0 + 1];
    float a00 = 0.f, a01 = 0.f, a10 = 0.f, a11 = 0.f;

    __syncthreads();

#pragma unroll
    for (int ii = 0; ii < ISEG; ++ii) {
        float2 mw  = *(const float2*)&MWs[ii][2 * tx];   // (o0, o0+1)
        float2 fx0 = fxs[ty][ii];                         // batch b0 (broadcast)
        float2 fx1 = fxs[ty + 4][ii];                     // batch b1 (broadcast)
        float t00 = tanh_fast(fx0.x * f2_00);
        float t01 = tanh_fast(fx0.x * f2_01);
        float t10 = tanh_fast(fx1.x * f2_10);
        float t11 = tanh_fast(fx1.x * f2_11);
        float w00 = __fmaf_rn(t00, 0.5f, 0.5f);
        float w01 = __fmaf_rn(t01, 0.5f, 0.5f);
        float w10 = __fmaf_rn(t10, 0.5f, 0.5f);
        float w11 = __fmaf_rn(t11, 0.5f, 0.5f);
        a00 = __fmaf_rn(w00, mw.x * fx0.y, a00);
        a01 = __fmaf_rn(w01, mw.y * fx0.y, a01);
        a10 = __fmaf_rn(w10, mw.x * fx1.y, a10);
        a11 = __fmaf_rn(w11, mw.y * fx1.y, a11);
    }

    float* p0 = partdst + (size_t)blockIdx.z * (64 * O) + b0 * O + o0;
    float* p1 = partdst + (size_t)blockIdx.z * (64 * O) + b1 * O + o0;
    *(float2*)p0 = make_float2(a00, a01);
    *(float2*)p1 = make_float2(a10, a11);
}

// ---------------- split-K dense reduce ----------------
template <int NS, int SZ>
__global__ void reduce_kernel(const float* __restrict__ src, float* __restrict__ dst) {
    int k = blockIdx.x * 256 + threadIdx.x;
    if (k < SZ) {
        float s = 0.f;
#pragma unroll
        for (int i = 0; i < NS; ++i)
            s += src[i * SZ + k];
        dst[k] = s;
    }
}

extern "C" void kernel_launch(void* const* d_in, const int* in_sizes, int n_in,
                              void* d_out, int out_size) {
    const float* x     = (const float*)d_in[0];
    const float* u     = (const float*)d_in[1];
    const float* mask0 = (const float*)d_in[2];
    const float* mask1 = (const float*)d_in[3];
    const float* mask2 = (const float*)d_in[4];
    const float* W0    = (const float*)d_in[5];
    const float* W1    = (const float*)d_in[6];
    const float* W2    = (const float*)d_in[7];
    const float* a0_w  = (const float*)d_in[8];
    const float* a0_b  = (const float*)d_in[9];
    const float* b0_w  = (const float*)d_in[10];
    const float* b0_b  = (const float*)d_in[11];
    const float* a1_w  = (const float*)d_in[12];
    const float* a1_b  = (const float*)d_in[13];
    const float* b1_w  = (const float*)d_in[14];
    const float* b1_b  = (const float*)d_in[15];
    const float* a2_w  = (const float*)d_in[16];
    const float* a2_b  = (const float*)d_in[17];
    const float* b2_w  = (const float*)d_in[18];
    const float* b2_b  = (const float*)d_in[19];
    float* out = (float*)d_out;

    float* pMW0;  cudaGetSymbolAddress((void**)&pMW0, g_MW0);
    float* pMW1;  cudaGetSymbolAddress((void**)&pMW1, g_MW1);
    float* pMW2;  cudaGetSymbolAddress((void**)&pMW2, g_MW2);
    float* pf1;   cudaGetSymbolAddress((void**)&pf1, g_f1a);
    float* pf2;   cudaGetSymbolAddress((void**)&pf2, g_f2a);
    float* pA;    cudaGetSymbolAddress((void**)&pA, g_partA);
    float* pB;    cudaGetSymbolAddress((void**)&pB, g_partB);
    float* ph1;   cudaGetSymbolAddress((void**)&ph1, g_h1);
    float* ph2;   cudaGetSymbolAddress((void**)&ph2, g_h2);

    // 1) MW = mask * W
    prep_mw_kernel<<<2048, 256>>>((const float4*)mask0, (const float4*)W0,
                                  (const float4*)mask1, (const float4*)W1,
                                  (const float4*)mask2, (const float4*)W2);

    // 2) all f1 / (0.5*f2) vectors
    cond_kernel<<<dim3(256, 6), 256>>>(u,
        a0_w, a0_b, b0_w, b0_b,
        a1_w, a1_b, b1_w, b1_b,
        a2_w, a2_b, b2_w, b2_b);

    // 3) layer 0: x(64x512) -> 16 partials in A ; reduce -> h1
    layer_kernel<512, 1024, 16><<<dim3(16, 8, 16), dim3(32, 4)>>>(
        x, pf1, pf2, pMW0, pA);
    reduce_kernel<16, 65536><<<256, 256>>>(pA, ph1);

    // 4) layer 1: h1 -> 32 partials in B ; reduce -> h2
    layer_kernel<1024, 1024, 32><<<dim3(16, 8, 32), dim3(32, 4)>>>(
        ph1, pf1 + 65536, pf2 + 65536, pMW1, pB);
    reduce_kernel<32, 65536><<<256, 256>>>(pB, ph2);

    // 5) layer 2: h2 -> 32 partials in A ; reduce -> d_out
    layer_kernel<1024, 512, 32><<<dim3(8, 8, 32), dim3(32, 4)>>>(
        ph2, pf1 + 131072, pf2 + 131072, pMW2, pA);
    reduce_kernel<32, 32768><<<128, 256>>>(pA, out);
}

// round 3
// speedup vs baseline: 1.3723x; 1.1107x over previous
#include <cuda_runtime.h>

// B=64, NIN=512, H1=H2=1024, NOUT=512, COND=64, FC=1
// out[b,o] = sum_i sigmoid(f1[b,i]*f2[b,o]) * (m*W)[o,i] * x[b,i]
// sigmoid(z) = 0.5 + 0.5*tanh(z/2); the 1/2 is folded into f2 at precompute.

// ---------------- device scratch ----------------
__device__ float g_MW0[1024 * 512];
__device__ float g_MW1[1024 * 1024];
__device__ float g_MW2[512 * 1024];
__device__ float g_f1a[3 * 64 * 1024];   // f1 per layer, slot stride 65536
__device__ float g_f2a[3 * 64 * 1024];   // 0.5*f2 per layer, slot stride 65536
__device__ float g_h1[65536];
__device__ float g_h2[65536];

__device__ __forceinline__ float tanh_fast(float x) {
    float r;
    asm("tanh.approx.f32 %0, %1;" : "=f"(r) : "f"(x));
    return r;
}

// ---------------- fused setup: MW=mask*W, cond GEMVs, zero h1/h2/out --------
// grid.x = 2048 (prep, float4) + 1536 (cond, 6*256) + 160 (zero) = 3744
__global__ void __launch_bounds__(256) setup_kernel(
    const float4* __restrict__ m0, const float4* __restrict__ w0f,
    const float4* __restrict__ m1, const float4* __restrict__ w1f,
    const float4* __restrict__ m2, const float4* __restrict__ w2f,
    const float* __restrict__ u,
    const float* __restrict__ cw0, const float* __restrict__ cb0,
    const float* __restrict__ cw1, const float* __restrict__ cb1,
    const float* __restrict__ cw2, const float* __restrict__ cb2,
    const float* __restrict__ cw3, const float* __restrict__ cb3,
    const float* __restrict__ cw4, const float* __restrict__ cb4,
    const float* __restrict__ cw5, const float* __restrict__ cb5,
    float4* __restrict__ outz) {
    __shared__ float us[64 * 65];
    int bid = blockIdx.x;
    int tid = threadIdx.x;

    if (bid < 2048) {
        // ---- MW = mask * W (float4) ----
        int idx = bid * 256 + tid;  // 0..524287
        float4 m, w; float4* dst;
        if (idx < 131072)      { m = m0[idx]; w = w0f[idx]; dst = (float4*)g_MW0 + idx; }
        else if (idx < 393216) { int k = idx - 131072; m = m1[k]; w = w1f[k]; dst = (float4*)g_MW1 + k; }
        else                   { int k = idx - 393216; m = m2[k]; w = w2f[k]; dst = (float4*)g_MW2 + k; }
        *dst = make_float4(m.x * w.x, m.y * w.y, m.z * w.z, m.w * w.w);
        return;
    }
    if (bid < 3584) {
        // ---- conditioning GEMVs ----
        int cbid = bid - 2048;
        int jblk = cbid & 255;
        int which = cbid >> 8;  // 0..5
        for (int k = tid; k < 64 * 64; k += 256)
            us[(k >> 6) * 65 + (k & 63)] = u[k];
        __syncthreads();

        const float* w; const float* bias;
        int J; float scale; float* dstp;
        switch (which) {
            case 0:  w = cw0; bias = cb0; J = 512;  scale = 1.0f; dstp = g_f1a;          break;
            case 1:  w = cw1; bias = cb1; J = 1024; scale = 0.5f; dstp = g_f2a;          break;
            case 2:  w = cw2; bias = cb2; J = 1024; scale = 1.0f; dstp = g_f1a + 65536;  break;
            case 3:  w = cw3; bias = cb3; J = 1024; scale = 0.5f; dstp = g_f2a + 65536;  break;
            case 4:  w = cw4; bias = cb4; J = 1024; scale = 1.0f; dstp = g_f1a + 131072; break;
            default: w = cw5; bias = cb5; J = 512;  scale = 0.5f; dstp = g_f2a + 131072; break;
        }
        int b = tid & 63;
        int jj = tid >> 6;
        int j = jblk * 4 + jj;
        if (j >= J) return;
        const float* wr = w + j * 64;
        float acc = 0.0f;
#pragma unroll
        for (int c = 0; c < 64; ++c)
            acc = __fmaf_rn(wr[c], us[b * 65 + c], acc);
        dstp[b * J + j] = (acc + bias[j]) * scale;
        return;
    }
    // ---- zero h1, h2, out ----
    {
        int idx = (bid - 3584) * 256 + tid;  // float4 units, 40960 total
        float4 z = make_float4(0.f, 0.f, 0.f, 0.f);
        if (idx < 16384)      ((float4*)g_h1)[idx] = z;
        else if (idx < 32768) ((float4*)g_h2)[idx - 16384] = z;
        else                  outz[idx - 32768] = z;
    }
}

// ---------------- main layer kernel (atomic accumulate) ----------------
// block (32,4). Thread: outputs oBase+2tx, oBase+2tx+1; batches bBase+ty+{0,4,8,12}.
// grid (O/64, 4, NS); ISEG = I/NS = 32 inputs per CTA. ILP-8 sigmoid chains.
// Results accumulated into hdst with atomicAdd (split-K over blockIdx.z).
template <int I, int O, int NS>
__global__ void __launch_bounds__(128) layer_kernel(
    const float* __restrict__ xsrc,
    const float* __restrict__ f1, const float* __restrict__ f2,
    const float* __restrict__ MW, float* __restrict__ hdst) {
    constexpr int ISEG = I / NS;          // 32
    constexpr int PITCH = 66;

    __shared__ float MWs[ISEG][PITCH];    // transposed [i][o]
    __shared__ float2 fxs[16][ISEG];      // [bb][ii] = (f1, x)

    int tx = threadIdx.x, ty = threadIdx.y;
    int tid = ty * 32 + tx;
    int oBase = blockIdx.x * 64;
    int bBase = blockIdx.y * 16;
    int iBase = blockIdx.z * ISEG;

    // stage MW tile transposed: float4 along i, scatter to [i][o]
    {
        int i4 = tid & 7;                 // ISEG/4 = 8
        int oo = tid >> 3;                // 0..15
#pragma unroll
        for (int r = 0; r < 4; ++r) {
            int o = oo + r * 16;
            float4 v = *(const float4*)(MW + (size_t)(oBase + o) * I + iBase + i4 * 4);
            MWs[i4 * 4 + 0][o] = v.x;
            MWs[i4 * 4 + 1][o] = v.y;
            MWs[i4 * 4 + 2][o] = v.z;
            MWs[i4 * 4 + 3][o] = v.w;
        }
    }
    // stage (f1, x): 16 batches x 32 inputs = 512 elements, 4 per thread
    {
#pragma unroll
        for (int r = 0; r < 4; ++r) {
            int k = tid + r * 128;
            int bb = k >> 5;
            int ii = k & 31;
            int b = bBase + bb;
            int gi = iBase + ii;
            fxs[bb][ii] = make_float2(f1[b * I + gi], xsrc[b * I + gi]);
        }
    }

    int o0 = oBase + 2 * tx;
    float2 f2r[4];
    float a[4][2];
#pragma unroll
    for (int r = 0; r < 4; ++r) {
        int b = bBase + ty + r * 4;
        f2r[r] = *(const float2*)(f2 + b * O + o0);
        a[r][0] = 0.f; a[r][1] = 0.f;
    }

    __syncthreads();

#pragma unroll
    for (int ii = 0; ii < ISEG; ++ii) {
        float2 mw = *(const float2*)&MWs[ii][2 * tx];
#pragma unroll
        for (int r = 0; r < 4; ++r) {
            float2 fx = fxs[ty + r * 4][ii];
            float t0 = tanh_fast(fx.x * f2r[r].x);
            float t1 = tanh_fast(fx.x * f2r[r].y);
            float s0 = __fmaf_rn(t0, 0.5f, 0.5f);
            float s1 = __fmaf_rn(t1, 0.5f, 0.5f);
            a[r][0] = __fmaf_rn(s0, mw.x * fx.y, a[r][0]);
            a[r][1] = __fmaf_rn(s1, mw.y * fx.y, a[r][1]);
        }
    }

#pragma unroll
    for (int r = 0; r < 4; ++r) {
        int b = bBase + ty + r * 4;
        atomicAdd(hdst + b * O + o0,     a[r][0]);
        atomicAdd(hdst + b * O + o0 + 1, a[r][1]);
    }
}

extern "C" void kernel_launch(void* const* d_in, const int* in_sizes, int n_in,
                              void* d_out, int out_size) {
    const float* x     = (const float*)d_in[0];
    const float* u     = (const float*)d_in[1];
    const float* mask0 = (const float*)d_in[2];
    const float* mask1 = (const float*)d_in[3];
    const float* mask2 = (const float*)d_in[4];
    const float* W0    = (const float*)d_in[5];
    const float* W1    = (const float*)d_in[6];
    const float* W2    = (const float*)d_in[7];
    const float* a0_w  = (const float*)d_in[8];
    const float* a0_b  = (const float*)d_in[9];
    const float* b0_w  = (const float*)d_in[10];
    const float* b0_b  = (const float*)d_in[11];
    const float* a1_w  = (const float*)d_in[12];
    const float* a1_b  = (const float*)d_in[13];
    const float* b1_w  = (const float*)d_in[14];
    const float* b1_b  = (const float*)d_in[15];
    const float* a2_w  = (const float*)d_in[16];
    const float* a2_b  = (const float*)d_in[17];
    const float* b2_w  = (const float*)d_in[18];
    const float* b2_b  = (const float*)d_in[19];
    float* out = (float*)d_out;

    float* pMW0;  cudaGetSymbolAddress((void**)&pMW0, g_MW0);
    float* pMW1;  cudaGetSymbolAddress((void**)&pMW1, g_MW1);
    float* pMW2;  cudaGetSymbolAddress((void**)&pMW2, g_MW2);
    float* pf1;   cudaGetSymbolAddress((void**)&pf1, g_f1a);
    float* pf2;   cudaGetSymbolAddress((void**)&pf2, g_f2a);
    float* ph1;   cudaGetSymbolAddress((void**)&ph1, g_h1);
    float* ph2;   cudaGetSymbolAddress((void**)&ph2, g_h2);

    // 1) fused setup: MW products + cond GEMVs + zero h1/h2/out
    setup_kernel<<<3744, 256>>>(
        (const float4*)mask0, (const float4*)W0,
        (const float4*)mask1, (const float4*)W1,
        (const float4*)mask2, (const float4*)W2,
        u,
        a0_w, a0_b, b0_w, b0_b,
        a1_w, a1_b, b1_w, b1_b,
        a2_w, a2_b, b2_w, b2_b,
        (float4*)out);

    // 2) layer 0: x(64x512) -> h1 (atomic split-K, NS=16)
    layer_kernel<512, 1024, 16><<<dim3(16, 4, 16), dim3(32, 4)>>>(
        x, pf1, pf2, pMW0, ph1);

    // 3) layer 1: h1 -> h2 (NS=32)
    layer_kernel<1024, 1024, 32><<<dim3(16, 4, 32), dim3(32, 4)>>>(
        ph1, pf1 + 65536, pf2 + 65536, pMW1, ph2);

    // 4) layer 2: h2 -> d_out (NS=32)
    layer_kernel<1024, 512, 32><<<dim3(8, 4, 32), dim3(32, 4)>>>(
        ph2, pf1 + 131072, pf2 + 131072, pMW2, out);
}

// round 4
// speedup vs baseline: 1.4171x; 1.0326x over previous
#include <cuda_runtime.h>

// B=64, NIN=512, H1=H2=1024, NOUT=512, COND=64, FC=1
// out[b,o] = sum_i sigmoid(f1[b,i]*f2[b,o]) * (m*W)[o,i] * x[b,i]
// sigmoid(z) = 0.5 + 0.5*tanh(z/2); the 1/2 is folded into f2 at precompute.
// Inner loop uses packed f32x2 math over batch pairs; tanh is scalar MUFU.

// ---------------- device scratch ----------------
__device__ float g_f1a[3 * 64 * 1024];   // f1 per layer, slot stride 65536
__device__ float g_f2a[3 * 64 * 1024];   // 0.5*f2 per layer, slot stride 65536
__device__ float g_h1[65536];
__device__ float g_h2[65536];

__device__ __forceinline__ float tanh_fast(float x) {
    float r;
    asm("tanh.approx.f32 %0, %1;" : "=f"(r) : "f"(x));
    return r;
}
__device__ __forceinline__ unsigned long long pack2(float lo, float hi) {
    unsigned long long r;
    asm("mov.b64 %0, {%1, %2};" : "=l"(r) : "f"(lo), "f"(hi));
    return r;
}
__device__ __forceinline__ void unpack2(float& lo, float& hi, unsigned long long v) {
    asm("mov.b64 {%0, %1}, %2;" : "=f"(lo), "=f"(hi) : "l"(v));
}
__device__ __forceinline__ unsigned long long mul2(unsigned long long a, unsigned long long b) {
    unsigned long long r;
    asm("mul.rn.f32x2 %0, %1, %2;" : "=l"(r) : "l"(a), "l"(b));
    return r;
}
__device__ __forceinline__ unsigned long long fma2(unsigned long long a, unsigned long long b,
                                                   unsigned long long c) {
    unsigned long long r;
    asm("fma.rn.f32x2 %0, %1, %2, %3;" : "=l"(r) : "l"(a), "l"(b), "l"(c));
    return r;
}

// ---------------- setup: cond GEMVs + zero h1/h2/out ----------------
// grid.x = 1536 (cond, 6*256) + 160 (zero) = 1696
__global__ void __launch_bounds__(256) setup_kernel(
    const float* __restrict__ u,
    const float* __restrict__ cw0, const float* __restrict__ cb0,
    const float* __restrict__ cw1, const float* __restrict__ cb1,
    const float* __restrict__ cw2, const float* __restrict__ cb2,
    const float* __restrict__ cw3, const float* __restrict__ cb3,
    const float* __restrict__ cw4, const float* __restrict__ cb4,
    const float* __restrict__ cw5, const float* __restrict__ cb5,
    float4* __restrict__ outz) {
    __shared__ float us[64 * 65];
    int bid = blockIdx.x;
    int tid = threadIdx.x;

    if (bid < 1536) {
        int jblk = bid & 255;
        int which = bid >> 8;  // 0..5
        for (int k = tid; k < 64 * 64; k += 256)
            us[(k >> 6) * 65 + (k & 63)] = u[k];
        __syncthreads();

        const float* w; const float* bias;
        int J; float scale; float* dstp;
        switch (which) {
            case 0:  w = cw0; bias = cb0; J = 512;  scale = 1.0f; dstp = g_f1a;          break;
            case 1:  w = cw1; bias = cb1; J = 1024; scale = 0.5f; dstp = g_f2a;          break;
            case 2:  w = cw2; bias = cb2; J = 1024; scale = 1.0f; dstp = g_f1a + 65536;  break;
            case 3:  w = cw3; bias = cb3; J = 1024; scale = 0.5f; dstp = g_f2a + 65536;  break;
            case 4:  w = cw4; bias = cb4; J = 1024; scale = 1.0f; dstp = g_f1a + 131072; break;
            default: w = cw5; bias = cb5; J = 512;  scale = 0.5f; dstp = g_f2a + 131072; break;
        }
        int b = tid & 63;
        int jj = tid >> 6;
        int j = jblk * 4 + jj;
        if (j >= J) return;
        const float* wr = w + j * 64;
        float acc = 0.0f;
#pragma unroll
        for (int c = 0; c < 64; ++c)
            acc = __fmaf_rn(wr[c], us[b * 65 + c], acc);
        dstp[b * J + j] = (acc + bias[j]) * scale;
        return;
    }
    // zero h1, h2, out : 40960 float4s
    {
        int idx = (bid - 1536) * 256 + tid;
        float4 z = make_float4(0.f, 0.f, 0.f, 0.f);
        if (idx < 16384)      ((float4*)g_h1)[idx] = z;
        else if (idx < 32768) ((float4*)g_h2)[idx - 16384] = z;
        else                  outz[idx - 32768] = z;
    }
}

// ---------------- main layer kernel ----------------
// CTA = 32 outputs (tx) x 32 batches (16 packed pairs) x ISEG inputs.
// Thread: output oBase+tx, batch pairs ty+4r (r=0..3) -> 8 sigmoid chains, f32x2-packed.
// grid (O/32, 2, NS); split-K accumulated into hdst via atomicAdd.
template <int I, int O, int NS>
__global__ void __launch_bounds__(128) layer_kernel(
    const float* __restrict__ xsrc,
    const float* __restrict__ f1, const float* __restrict__ f2,
    const float* __restrict__ mask, const float* __restrict__ W,
    float* __restrict__ hdst) {
    constexpr int ISEG = I / NS;      // 16 or 32
    constexpr int PITCH = 33;

    __shared__ float MWs[ISEG][PITCH];            // [i][o], mask*W
    __shared__ unsigned long long fps[16][ISEG];  // packed f1 batch-pairs
    __shared__ unsigned long long xps[16][ISEG];  // packed x  batch-pairs

    int tx = threadIdx.x, ty = threadIdx.y;
    int tid = ty * 32 + tx;
    int oBase = blockIdx.x * 32;
    int bBase = blockIdx.y * 32;
    int iBase = blockIdx.z * ISEG;

    // stage MW = mask * W, transposed [i][o]
    constexpr int NF4 = ISEG / 4;
    for (int k = tid; k < 32 * NF4; k += 128) {
        int o = k / NF4, i4 = k % NF4;
        size_t off = (size_t)(oBase + o) * I + iBase + i4 * 4;
        float4 mv = *(const float4*)(mask + off);
        float4 wv = *(const float4*)(W + off);
        MWs[i4 * 4 + 0][o] = mv.x * wv.x;
        MWs[i4 * 4 + 1][o] = mv.y * wv.y;
        MWs[i4 * 4 + 2][o] = mv.z * wv.z;
        MWs[i4 * 4 + 3][o] = mv.w * wv.w;
    }
    // stage packed (f1, x) batch-pairs
    for (int k = tid; k < 16 * ISEG; k += 128) {
        int pr = k / ISEG, ii = k % ISEG;
        int b = bBase + 2 * pr;
        int gi = iBase + ii;
        fps[pr][ii] = pack2(f1[b * I + gi], f1[(b + 1) * I + gi]);
        xps[pr][ii] = pack2(xsrc[b * I + gi], xsrc[(b + 1) * I + gi]);
    }

    int o = oBase + tx;
    unsigned long long f2p[4], acc[4];
#pragma unroll
    for (int r = 0; r < 4; ++r) {
        int b = bBase + 2 * (ty + 4 * r);
        f2p[r] = pack2(f2[b * O + o], f2[(b + 1) * O + o]);
        acc[r] = 0ULL;  // {+0.0f, +0.0f}
    }
    const unsigned long long H = 0x3f0000003f000000ULL;  // {0.5f, 0.5f}

    __syncthreads();

#pragma unroll
    for (int ii = 0; ii < ISEG; ++ii) {
        float mw = MWs[ii][tx];
        unsigned long long mwd = pack2(mw, mw);
#pragma unroll
        for (int r = 0; r < 4; ++r) {
            int pr = ty + 4 * r;
            unsigned long long z = mul2(fps[pr][ii], f2p[r]);
            float z0, z1;
            unpack2(z0, z1, z);
            unsigned long long tp = pack2(tanh_fast(z0), tanh_fast(z1));
            unsigned long long s = fma2(tp, H, H);          // sigmoid = 0.5 + 0.5*tanh
            unsigned long long p = mul2(mwd, xps[pr][ii]);  // (m*W)*x
            acc[r] = fma2(s, p, acc[r]);
        }
    }

#pragma unroll
    for (int r = 0; r < 4; ++r) {
        int b = bBase + 2 * (ty + 4 * r);
        float a0, a1;
        unpack2(a0, a1, acc[r]);
        atomicAdd(hdst + b * O + o, a0);
        atomicAdd(hdst + (b + 1) * O + o, a1);
    }
}

extern "C" void kernel_launch(void* const* d_in, const int* in_sizes, int n_in,
                              void* d_out, int out_size) {
    const float* x     = (const float*)d_in[0];
    const float* u     = (const float*)d_in[1];
    const float* mask0 = (const float*)d_in[2];
    const float* mask1 = (const float*)d_in[3];
    const float* mask2 = (const float*)d_in[4];
    const float* W0    = (const float*)d_in[5];
    const float* W1    = (const float*)d_in[6];
    const float* W2    = (const float*)d_in[7];
    const float* a0_w  = (const float*)d_in[8];
    const float* a0_b  = (const float*)d_in[9];
    const float* b0_w  = (const float*)d_in[10];
    const float* b0_b  = (const float*)d_in[11];
    const float* a1_w  = (const float*)d_in[12];
    const float* a1_b  = (const float*)d_in[13];
    const float* b1_w  = (const float*)d_in[14];
    const float* b1_b  = (const float*)d_in[15];
    const float* a2_w  = (const float*)d_in[16];
    const float* a2_b  = (const float*)d_in[17];
    const float* b2_w  = (const float*)d_in[18];
    const float* b2_b  = (const float*)d_in[19];
    float* out = (float*)d_out;

    float* pf1;  cudaGetSymbolAddress((void**)&pf1, g_f1a);
    float* pf2;  cudaGetSymbolAddress((void**)&pf2, g_f2a);
    float* ph1;  cudaGetSymbolAddress((void**)&ph1, g_h1);
    float* ph2;  cudaGetSymbolAddress((void**)&ph2, g_h2);

    // 1) setup: cond GEMVs + zero h1/h2/out
    setup_kernel<<<1696, 256>>>(u,
        a0_w, a0_b, b0_w, b0_b,
        a1_w, a1_b, b1_w, b1_b,
        a2_w, a2_b, b2_w, b2_b,
        (float4*)out);

    // 2) layer 0: x(64x512) -> h1 ; ISEG=16, 2048 CTAs
    layer_kernel<512, 1024, 32><<<dim3(32, 2, 32), dim3(32, 4)>>>(
        x, pf1, pf2, mask0, W0, ph1);

    // 3) layer 1: h1 -> h2 ; ISEG=32, 2048 CTAs
    layer_kernel<1024, 1024, 32><<<dim3(32, 2, 32), dim3(32, 4)>>>(
        ph1, pf1 + 65536, pf2 + 65536, mask1, W1, ph2);

    // 4) layer 2: h2 -> d_out ; ISEG=16, 2048 CTAs
    layer_kernel<1024, 512, 64><<<dim3(16, 2, 64), dim3(32, 4)>>>(
        ph2, pf1 + 131072, pf2 + 131072, mask2, W2, out);
}